// round 12
// baseline (speedup 1.0000x reference)
#include <cuda_runtime.h>
#include <cuda_fp16.h>
#include <cstdint>

// ---------------------------------------------------------------------------
// InflateHexToVertex, factored:
//   Z[j,t,b,v] = hex[b,t,:] @ W[j*D:(j+1)*D, :]   (mma.sync fp16 GEMM, f32 acc)
//   out[b,n,v] = bias[v] + sum_j (idx[n,j] >= 0) * Z[j, idx[n,j], b, v]
//
// Z fp16 (12.6 MB), L2-resident. Gather: WARP-PER-VERTEX, no block sync, no
// smem -- per-warp ballot dtype detect, shfl-broadcast indices, 6 Z-loads in
// flight. GEMM: R8 config (64KB smem, 2 blocks/SM, per-j staging).
// ---------------------------------------------------------------------------

__device__ __half g_Zh[3 * 512 * 32 * 128];

#define OFF_A 0
#define OFF_B 32768
#define GEMM_SMEM 65536

__device__ __forceinline__ uint32_t smem_u32(const void* p) {
    uint32_t a;
    asm("{ .reg .u64 t; cvta.to.shared.u64 t, %1; cvt.u32.u64 %0, t; }"
        : "=r"(a) : "l"(p));
    return a;
}

// --- Z = hex(16384x128) @ W(384x128) via mma.sync (R8 config) -----------------
__global__ void __launch_bounds__(256, 2)
gemm_z(const float* __restrict__ A, const float* __restrict__ W,
       int T, int B) {
    extern __shared__ char sm[];
    const uint32_t smb = smem_u32(sm);
    const int tid = threadIdx.x;
    const int wid = tid >> 5;
    const int lane = tid & 31;
    const int m0 = blockIdx.x * 128;

    #pragma unroll
    for (int it = 0; it < 8; ++it) {
        int p   = it * 256 + tid;
        int row = p >> 4;
        int c   = p & 15;
        const float* src = A + (size_t)(m0 + row) * 128 + c * 8;
        float4 f0 = *(const float4*)src;
        float4 f1 = *(const float4*)(src + 4);
        __half2 h[4] = {__floats2half2_rn(f0.x, f0.y), __floats2half2_rn(f0.z, f0.w),
                        __floats2half2_rn(f1.x, f1.y), __floats2half2_rn(f1.z, f1.w)};
        *(uint4*)(sm + OFF_A + row * 256 + ((c ^ (row & 7)) << 4)) = *(uint4*)h;
    }

    const int arow = wid * 16 + (lane & 15);
    const uint32_t a_base = smb + OFF_A + arow * 256;
    const int a_hi = lane >> 4;
    const int a_r7 = arow & 7;
    const uint32_t b_base = smb + OFF_B + (lane & 15) * 256;
    const int b_hi = lane >> 4;
    const int b_r7 = lane & 7;

    const int r  = lane >> 2;
    const int q2 = (lane & 3) * 2;
    const int mA = m0 + wid * 16 + r;
    const int mB = mA + 8;
    const int bA = mA / T, tA = mA - bA * T;
    const int bB = mB / T, tB = mB - bB * T;

    for (int j = 0; j < 3; ++j) {
        #pragma unroll
        for (int it = 0; it < 8; ++it) {
            int p  = it * 256 + tid;
            int k  = p >> 4;
            int cn = p & 15;
            const float* src = W + ((size_t)j * 128 + k) * 128 + cn * 8;
            float4 f0 = *(const float4*)src;
            float4 f1 = *(const float4*)(src + 4);
            __half2 h[4] = {__floats2half2_rn(f0.x, f0.y), __floats2half2_rn(f0.z, f0.w),
                            __floats2half2_rn(f1.x, f1.y), __floats2half2_rn(f1.z, f1.w)};
            *(uint4*)(sm + OFF_B + k * 256 + ((cn ^ (k & 7)) << 4)) = *(uint4*)h;
        }
        __syncthreads();

        float c[16][4];
        #pragma unroll
        for (int nb = 0; nb < 16; ++nb)
            #pragma unroll
            for (int q = 0; q < 4; ++q) c[nb][q] = 0.f;

        #pragma unroll
        for (int kb = 0; kb < 8; ++kb) {
            uint32_t a0, a1, a2, a3;
            uint32_t a_addr = a_base + (((2 * kb + a_hi) ^ a_r7) << 4);
            asm volatile("ldmatrix.sync.aligned.m8n8.x4.shared.b16 {%0,%1,%2,%3}, [%4];"
                         : "=r"(a0), "=r"(a1), "=r"(a2), "=r"(a3) : "r"(a_addr));
            #pragma unroll
            for (int nb2 = 0; nb2 < 8; ++nb2) {
                uint32_t b0, b1, b2, b3;
                uint32_t b_addr = b_base + kb * 4096
                                + (((2 * nb2 + b_hi) ^ b_r7) << 4);
                asm volatile("ldmatrix.sync.aligned.m8n8.x4.trans.shared.b16 "
                             "{%0,%1,%2,%3}, [%4];"
                             : "=r"(b0), "=r"(b1), "=r"(b2), "=r"(b3) : "r"(b_addr));
                asm volatile(
                    "mma.sync.aligned.m16n8k16.row.col.f32.f16.f16.f32 "
                    "{%0,%1,%2,%3}, {%4,%5,%6,%7}, {%8,%9}, {%0,%1,%2,%3};"
                    : "+f"(c[2*nb2][0]), "+f"(c[2*nb2][1]),
                      "+f"(c[2*nb2][2]), "+f"(c[2*nb2][3])
                    : "r"(a0), "r"(a1), "r"(a2), "r"(a3), "r"(b0), "r"(b1));
                asm volatile(
                    "mma.sync.aligned.m16n8k16.row.col.f32.f16.f16.f32 "
                    "{%0,%1,%2,%3}, {%4,%5,%6,%7}, {%8,%9}, {%0,%1,%2,%3};"
                    : "+f"(c[2*nb2+1][0]), "+f"(c[2*nb2+1][1]),
                      "+f"(c[2*nb2+1][2]), "+f"(c[2*nb2+1][3])
                    : "r"(a0), "r"(a1), "r"(a2), "r"(a3), "r"(b2), "r"(b3));
            }
        }

        __half* dstA = g_Zh + (((size_t)j * T + tA) * B + bA) * 128 + q2;
        __half* dstB = g_Zh + (((size_t)j * T + tB) * B + bB) * 128 + q2;
        #pragma unroll
        for (int nb = 0; nb < 16; ++nb) {
            *(__half2*)(dstA + nb * 8) = __floats2half2_rn(c[nb][0], c[nb][1]);
            *(__half2*)(dstB + nb * 8) = __floats2half2_rn(c[nb][2], c[nb][3]);
        }
        __syncthreads();
    }
}

// --- out[b,n,:] = bias + sum_j Z[j, idx[n,j], b, :] --------------------------
// Warp-per-vertex: no smem, no __syncthreads. Lane l covers v8 = l&15 (fixed)
// and b = (l>>4) + 2*it over 16 iterations, unrolled x2 -> 6 loads in flight.
__global__ void __launch_bounds__(256)
gather_out(const int* __restrict__ idxw,
           const float* __restrict__ bias,
           float* __restrict__ out, int N, int T, int B) {
    const int lane = threadIdx.x & 31;
    const int n = blockIdx.x * 8 + (threadIdx.x >> 5);

    // int64 little-endian => every odd word is the sign extension of the even
    // word; int32 data with values in [-1,T) fails this w.p. ~1. L1-hits after
    // the first warp on each SM.
    int lo = idxw[2 * lane];
    int hi = idxw[2 * lane + 1];
    unsigned ok = __ballot_sync(0xffffffffu, hi == ((lo < 0) ? -1 : 0));
    const int s = 1 + (ok == 0xffffffffu);

    int tl = (lane < 3) ? idxw[(n * 3 + lane) * s] : 0;
    const int t0 = __shfl_sync(0xffffffffu, tl, 0);
    const int t1 = __shfl_sync(0xffffffffu, tl, 1);
    const int t2 = __shfl_sync(0xffffffffu, tl, 2);

    const uint4*  Z16 = (const uint4*)g_Zh;
    const float4* b4  = (const float4*)bias;
    const uint4   zz  = make_uint4(0u, 0u, 0u, 0u);

    const int v8 = lane & 15;
    const float4 bsA = __ldg(b4 + v8 * 2);
    const float4 bsB = __ldg(b4 + v8 * 2 + 1);

    const int rows = B * 16;                 // uint4 per (j,t) row
    const size_t r0 = (size_t)(0 * T + (t0 < 0 ? 0 : t0)) * rows;
    const size_t r1 = (size_t)(1 * T + (t1 < 0 ? 0 : t1)) * rows;
    const size_t r2 = (size_t)(2 * T + (t2 < 0 ? 0 : t2)) * rows;

    float* const obase = out + (size_t)n * 128 + v8 * 8;
    const size_t ostride = (size_t)N * 128;  // per-b stride in floats

    #pragma unroll
    for (int it2 = 0; it2 < 8; ++it2) {
        const int b0 = (lane >> 4) + 4 * it2;
        const int b1 = b0 + 2;
        const size_t o0 = (size_t)b0 * 16 + v8;
        const size_t o1 = (size_t)b1 * 16 + v8;

        // 6 loads in flight (3 per b), conditional like the measured-best R6.
        uint4 z[6];
        z[0] = (t0 >= 0) ? __ldcg(Z16 + r0 + o0) : zz;
        z[1] = (t1 >= 0) ? __ldcg(Z16 + r1 + o0) : zz;
        z[2] = (t2 >= 0) ? __ldcg(Z16 + r2 + o0) : zz;
        z[3] = (t0 >= 0) ? __ldcg(Z16 + r0 + o1) : zz;
        z[4] = (t1 >= 0) ? __ldcg(Z16 + r1 + o1) : zz;
        z[5] = (t2 >= 0) ? __ldcg(Z16 + r2 + o1) : zz;

        #pragma unroll
        for (int h = 0; h < 2; ++h) {
            float4 accA = bsA, accB = bsB;
            #pragma unroll
            for (int j = 0; j < 3; ++j) {
                const uint4 zv = z[h * 3 + j];
                float2 f0 = __half22float2(*(__half2*)&zv.x);
                float2 f1 = __half22float2(*(__half2*)&zv.y);
                float2 f2 = __half22float2(*(__half2*)&zv.z);
                float2 f3 = __half22float2(*(__half2*)&zv.w);
                accA.x += f0.x; accA.y += f0.y; accA.z += f1.x; accA.w += f1.y;
                accB.x += f2.x; accB.y += f2.y; accB.z += f3.x; accB.w += f3.y;
            }
            float* o = obase + (size_t)(h ? b1 : b0) * ostride;
            __stcs((float4*)o, accA);
            __stcs((float4*)(o + 4), accB);
        }
    }
}

extern "C" void kernel_launch(void* const* d_in, const int* in_sizes, int n_in,
                              void* d_out, int out_size) {
    const float* hex  = (const float*)d_in[0];   // (B, T, D) f32
    const int*   idxw = (const int*)d_in[1];     // (N, 3) int32 or int64
    const float* W    = (const float*)d_in[2];   // (3D, V) f32
    const float* bias = (const float*)d_in[3];   // (V,) f32
    float*       out  = (float*)d_out;           // (B, N, V) f32

    const int V      = in_sizes[3];              // 128
    const int threeD = in_sizes[2] / V;          // 384
    const int D      = threeD / 3;               // 128
    const int BT     = in_sizes[0] / D;          // B*T = 16384
    const int N      = in_sizes[1] / 3;          // 20000
    const int B      = out_size / (N * V);       // 32
    const int T      = BT / B;                   // 512

    cudaFuncSetAttribute(gemm_z, cudaFuncAttributeMaxDynamicSharedMemorySize,
                         GEMM_SMEM);

    gemm_z<<<BT / 128, 256, GEMM_SMEM>>>(hex, W, T, B);

    gather_out<<<N / 8, 256>>>(idxw, bias, out, N, T, B);
}

// round 13
// speedup vs baseline: 1.0803x; 1.0803x over previous
#include <cuda_runtime.h>
#include <cuda_fp16.h>
#include <cstdint>

// ---------------------------------------------------------------------------
// InflateHexToVertex, factored:
//   Z[j,t,b,v] = hex[b,t,:] @ W[j*D:(j+1)*D, :]   (mma.sync fp16 GEMM, f32 acc)
//   out[b,n,v] = bias[v] + sum_j (idx[n,j] >= 0) * Z[j, idx[n,j], b, v]
//
// Z fp16 (12.6 MB), L2-resident. GEMM: M=64 tiles (grid 256, 4 warps, 48KB
// smem, 4 blocks/SM) so all 148 SMs carry work. Gather: R6 shape (256 thr,
// 2 vertices, 6 loads in flight) -- measured optimum across 7 variants.
// ---------------------------------------------------------------------------

__device__ __half g_Zh[3 * 512 * 32 * 128];

#define OFF_A 0
#define OFF_B 16384
#define GEMM_SMEM 49152

__device__ __forceinline__ uint32_t smem_u32(const void* p) {
    uint32_t a;
    asm("{ .reg .u64 t; cvta.to.shared.u64 t, %1; cvt.u32.u64 %0, t; }"
        : "=r"(a) : "l"(p));
    return a;
}

// --- Z = hex(16384x128) @ W(384x128) via mma.sync ----------------------------
// Grid BT/64, 128 threads (4 warps). Stage 64-row A tile once; for j=0..2
// stage W_j, compute 64x128, write Z_j. Warp w owns rows w*16..w*16+15.
__global__ void __launch_bounds__(128, 4)
gemm_z(const float* __restrict__ A, const float* __restrict__ W,
       int T, int B) {
    extern __shared__ char sm[];
    const uint32_t smb = smem_u32(sm);
    const int tid = threadIdx.x;
    const int wid = tid >> 5;
    const int lane = tid & 31;
    const int m0 = blockIdx.x * 64;

    // ---- stage A tile (64x128): fp32 -> fp16, swizzled -----------------------
    #pragma unroll
    for (int it = 0; it < 8; ++it) {
        int p   = it * 128 + tid;          // 1024 chunks
        int row = p >> 4;
        int c   = p & 15;
        const float* src = A + (size_t)(m0 + row) * 128 + c * 8;
        float4 f0 = *(const float4*)src;
        float4 f1 = *(const float4*)(src + 4);
        __half2 h[4] = {__floats2half2_rn(f0.x, f0.y), __floats2half2_rn(f0.z, f0.w),
                        __floats2half2_rn(f1.x, f1.y), __floats2half2_rn(f1.z, f1.w)};
        *(uint4*)(sm + OFF_A + row * 256 + ((c ^ (row & 7)) << 4)) = *(uint4*)h;
    }

    // ldmatrix lane addressing
    const int arow = wid * 16 + (lane & 15);
    const uint32_t a_base = smb + OFF_A + arow * 256;
    const int a_hi = lane >> 4;
    const int a_r7 = arow & 7;
    const uint32_t b_base = smb + OFF_B + (lane & 15) * 256;
    const int b_hi = lane >> 4;            // x4.trans: upper half-warp -> chunk+1
    const int b_r7 = lane & 7;

    // epilogue coords
    const int r  = lane >> 2;
    const int q2 = (lane & 3) * 2;
    const int mA = m0 + wid * 16 + r;
    const int mB = mA + 8;
    const int bA = mA / T, tA = mA - bA * T;
    const int bB = mB / T, tB = mB - bB * T;

    for (int j = 0; j < 3; ++j) {
        // ---- stage B_j (128x128): W[j*128 + k][v], fp32 -> fp16, swizzled ----
        #pragma unroll
        for (int it = 0; it < 16; ++it) {
            int p  = it * 128 + tid;       // 2048 chunks
            int k  = p >> 4;
            int cn = p & 15;
            const float* src = W + ((size_t)j * 128 + k) * 128 + cn * 8;
            float4 f0 = *(const float4*)src;
            float4 f1 = *(const float4*)(src + 4);
            __half2 h[4] = {__floats2half2_rn(f0.x, f0.y), __floats2half2_rn(f0.z, f0.w),
                            __floats2half2_rn(f1.x, f1.y), __floats2half2_rn(f1.z, f1.w)};
            *(uint4*)(sm + OFF_B + k * 256 + ((cn ^ (k & 7)) << 4)) = *(uint4*)h;
        }
        __syncthreads();

        float c[16][4];
        #pragma unroll
        for (int nb = 0; nb < 16; ++nb)
            #pragma unroll
            for (int q = 0; q < 4; ++q) c[nb][q] = 0.f;

        #pragma unroll
        for (int kb = 0; kb < 8; ++kb) {
            uint32_t a0, a1, a2, a3;
            uint32_t a_addr = a_base + (((2 * kb + a_hi) ^ a_r7) << 4);
            asm volatile("ldmatrix.sync.aligned.m8n8.x4.shared.b16 {%0,%1,%2,%3}, [%4];"
                         : "=r"(a0), "=r"(a1), "=r"(a2), "=r"(a3) : "r"(a_addr));
            #pragma unroll
            for (int nb2 = 0; nb2 < 8; ++nb2) {
                uint32_t b0, b1, b2, b3;
                uint32_t b_addr = b_base + kb * 4096
                                + (((2 * nb2 + b_hi) ^ b_r7) << 4);
                asm volatile("ldmatrix.sync.aligned.m8n8.x4.trans.shared.b16 "
                             "{%0,%1,%2,%3}, [%4];"
                             : "=r"(b0), "=r"(b1), "=r"(b2), "=r"(b3) : "r"(b_addr));
                asm volatile(
                    "mma.sync.aligned.m16n8k16.row.col.f32.f16.f16.f32 "
                    "{%0,%1,%2,%3}, {%4,%5,%6,%7}, {%8,%9}, {%0,%1,%2,%3};"
                    : "+f"(c[2*nb2][0]), "+f"(c[2*nb2][1]),
                      "+f"(c[2*nb2][2]), "+f"(c[2*nb2][3])
                    : "r"(a0), "r"(a1), "r"(a2), "r"(a3), "r"(b0), "r"(b1));
                asm volatile(
                    "mma.sync.aligned.m16n8k16.row.col.f32.f16.f16.f32 "
                    "{%0,%1,%2,%3}, {%4,%5,%6,%7}, {%8,%9}, {%0,%1,%2,%3};"
                    : "+f"(c[2*nb2+1][0]), "+f"(c[2*nb2+1][1]),
                      "+f"(c[2*nb2+1][2]), "+f"(c[2*nb2+1][3])
                    : "r"(a0), "r"(a1), "r"(a2), "r"(a3), "r"(b2), "r"(b3));
            }
        }

        // ---- epilogue: cvt fp16, write Z[j][t][b][v] --------------------------
        __half* dstA = g_Zh + (((size_t)j * T + tA) * B + bA) * 128 + q2;
        __half* dstB = g_Zh + (((size_t)j * T + tB) * B + bB) * 128 + q2;
        #pragma unroll
        for (int nb = 0; nb < 16; ++nb) {
            *(__half2*)(dstA + nb * 8) = __floats2half2_rn(c[nb][0], c[nb][1]);
            *(__half2*)(dstB + nb * 8) = __floats2half2_rn(c[nb][2], c[nb][3]);
        }
        __syncthreads();   // protect Bs before restaging
    }
}

// --- out[b,n,:] = bias + sum_j Z[j, idx[n,j], b, :] --------------------------
// R6 shape: 2 vertices per block, 256 threads, 6 Z-loads in flight. 83.3 us.
__global__ void gather_out(const int* __restrict__ idxw,
                           const float* __restrict__ bias,
                           float* __restrict__ out, int N, int T, int B) {
    __shared__ int sh_t[6];
    const int n0 = blockIdx.x * 2;

    if (threadIdx.x < 32) {
        // int64 little-endian => every odd word is the sign extension of the
        // preceding word; int32 data with values in [-1,T) fails w.p. ~1.
        int lo = idxw[2 * threadIdx.x];
        int hi = idxw[2 * threadIdx.x + 1];
        unsigned ok = __ballot_sync(0xffffffffu, hi == ((lo < 0) ? -1 : 0));
        int s = 1 + (ok == 0xffffffffu);
        if (threadIdx.x < 6) sh_t[threadIdx.x] = idxw[(n0 * 3 + threadIdx.x) * s];
    }
    __syncthreads();

    int tt[6];
    #pragma unroll
    for (int i = 0; i < 6; ++i) tt[i] = sh_t[i];

    const uint4*  Z16 = (const uint4*)g_Zh;
    const float4* b4  = (const float4*)bias;
    const uint4   zz  = make_uint4(0u, 0u, 0u, 0u);

    const int total = B * 16;                 // 512 items per vertex pair
    for (int p = threadIdx.x; p < total; p += blockDim.x) {
        const int b  = p >> 4;
        const int v8 = p & 15;
        const size_t rowoff = (size_t)b * 16 + v8;

        uint4 z[6];
        #pragma unroll
        for (int i = 0; i < 6; ++i) {
            int j = i % 3;
            int t = tt[i];
            z[i] = (t >= 0)
                 ? __ldcg(Z16 + ((size_t)j * T + t) * (B * 16) + rowoff)
                 : zz;
        }

        float4 bsA = __ldg(b4 + v8 * 2);
        float4 bsB = __ldg(b4 + v8 * 2 + 1);

        #pragma unroll
        for (int nn = 0; nn < 2; ++nn) {
            float4 accA = bsA, accB = bsB;
            #pragma unroll
            for (int j = 0; j < 3; ++j) {
                uint4 zv = z[nn * 3 + j];
                float2 f0 = __half22float2(*(__half2*)&zv.x);
                float2 f1 = __half22float2(*(__half2*)&zv.y);
                float2 f2 = __half22float2(*(__half2*)&zv.z);
                float2 f3 = __half22float2(*(__half2*)&zv.w);
                accA.x += f0.x; accA.y += f0.y; accA.z += f1.x; accA.w += f1.y;
                accB.x += f2.x; accB.y += f2.y; accB.z += f3.x; accB.w += f3.y;
            }
            float* o = out + ((size_t)b * N + (n0 + nn)) * 128 + v8 * 8;
            __stcs((float4*)o, accA);
            __stcs((float4*)(o + 4), accB);
        }
    }
}

extern "C" void kernel_launch(void* const* d_in, const int* in_sizes, int n_in,
                              void* d_out, int out_size) {
    const float* hex  = (const float*)d_in[0];   // (B, T, D) f32
    const int*   idxw = (const int*)d_in[1];     // (N, 3) int32 or int64
    const float* W    = (const float*)d_in[2];   // (3D, V) f32
    const float* bias = (const float*)d_in[3];   // (V,) f32
    float*       out  = (float*)d_out;           // (B, N, V) f32

    const int V      = in_sizes[3];              // 128
    const int threeD = in_sizes[2] / V;          // 384
    const int D      = threeD / 3;               // 128
    const int BT     = in_sizes[0] / D;          // B*T = 16384
    const int N      = in_sizes[1] / 3;          // 20000
    const int B      = out_size / (N * V);       // 32
    const int T      = BT / B;                   // 512

    cudaFuncSetAttribute(gemm_z, cudaFuncAttributeMaxDynamicSharedMemorySize,
                         GEMM_SMEM);

    gemm_z<<<BT / 64, 128, GEMM_SMEM>>>(hex, W, T, B);

    gather_out<<<N / 2, 256>>>(idxw, bias, out, N, T, B);
}